// round 5
// baseline (speedup 1.0000x reference)
#include <cuda_runtime.h>
#include <cstdint>
#include <cstddef>

#define N_NODES 50000
#define N_EDGES 800000

// Scratch (device globals: no allocation allowed)
__device__ __align__(16) float g_xw1[N_NODES * 64];   // x@W1[:64]+b1, later agg_mean@W2 result
__device__ __align__(16) float g_agg[N_NODES * 64];   // per-node sum of relu(h)
__device__ int g_cnt[N_NODES];                        // in-degree counts
__device__ int g_base[N_NODES];                       // exclusive prefix of counts
__device__ int g_cursor[N_NODES];                     // placement cursors
__device__ int g_psrc[N_EDGES];                       // src node, sorted by dst
__device__ int g_pe[N_EDGES];                         // edge id, sorted by dst

typedef unsigned long long u64;

__device__ __forceinline__ u64 pack2(float v) {
    u64 r; asm("mov.b64 %0, {%1, %1};" : "=l"(r) : "f"(v)); return r;
}
__device__ __forceinline__ void unpack2(u64 v, float &lo, float &hi) {
    asm("mov.b64 {%0, %1}, %2;" : "=f"(lo), "=f"(hi) : "l"(v));
}
__device__ __forceinline__ void ffma2(u64 &d, u64 a, u64 b) {
    asm("fma.rn.f32x2 %0, %1, %2, %0;" : "+l"(d) : "l"(a), "l"(b));
}

// ---------------------------------------------------------------------------
// K1: g_xw1[n] = x[n] @ W1[0:64,:] + b1 ; zero g_cnt.
// ---------------------------------------------------------------------------
__global__ void __launch_bounds__(128) precompute_kernel(
        const float* __restrict__ x,
        const float* __restrict__ W1,
        const float* __restrict__ b1) {
    __shared__ ulonglong2 sW[64 * 16];   // 16 KB
    __shared__ ulonglong2 sb[16];
    int tid = threadIdx.x;
    const ulonglong2* W1v = reinterpret_cast<const ulonglong2*>(W1);
    for (int idx = tid; idx < 64 * 16; idx += 128) sW[idx] = W1v[idx];
    if (tid < 16) sb[tid] = reinterpret_cast<const ulonglong2*>(b1)[tid];
    __syncthreads();

    int n = blockIdx.x * 128 + tid;
    if (n >= N_NODES) return;

    u64 acc[32];
    #pragma unroll
    for (int j = 0; j < 16; j++) { ulonglong2 v = sb[j]; acc[2*j] = v.x; acc[2*j+1] = v.y; }

    const float4* xr = reinterpret_cast<const float4*>(x + (size_t)n * 64);
    #pragma unroll 1
    for (int c = 0; c < 2; c++) {
        float v[32];
        #pragma unroll
        for (int j = 0; j < 8; j++) {
            float4 f = xr[c * 8 + j];
            v[4*j] = f.x; v[4*j+1] = f.y; v[4*j+2] = f.z; v[4*j+3] = f.w;
        }
        #pragma unroll
        for (int i = 0; i < 32; i++) {
            u64 a = pack2(v[i]);
            #pragma unroll
            for (int j = 0; j < 16; j++) {
                ulonglong2 w = sW[(c * 32 + i) * 16 + j];
                ffma2(acc[2*j], a, w.x);
                ffma2(acc[2*j+1], a, w.y);
            }
        }
    }
    ulonglong2* o = reinterpret_cast<ulonglong2*>(g_xw1 + (size_t)n * 64);
    #pragma unroll
    for (int j = 0; j < 16; j++) {
        ulonglong2 v; v.x = acc[2*j]; v.y = acc[2*j+1]; o[j] = v;
    }
    g_cnt[n] = 0;
}

// ---------------------------------------------------------------------------
// K2: count in-degrees (int atomics, L2-resident 200 KB table)
// ---------------------------------------------------------------------------
__global__ void __launch_bounds__(256) count_kernel(const int* __restrict__ ei) {
    int e = blockIdx.x * 256 + threadIdx.x;   // N_EDGES % 256 == 0
    atomicAdd(&g_cnt[ei[N_EDGES + e]], 1);
}

// ---------------------------------------------------------------------------
// K3: exclusive prefix sum of g_cnt -> g_base, g_cursor. One block.
// ---------------------------------------------------------------------------
__global__ void __launch_bounds__(1024) scan_kernel() {
    __shared__ int warpsum[32];
    int tid = threadIdx.x;
    const int CH = (N_NODES + 1023) / 1024;   // 49
    int start = tid * CH;

    int s = 0;
    for (int k = 0; k < CH; k++) {
        int idx = start + k;
        if (idx < N_NODES) s += g_cnt[idx];
    }
    int lane = tid & 31, w = tid >> 5;
    int v = s;
    #pragma unroll
    for (int o = 1; o < 32; o <<= 1) {
        int t = __shfl_up_sync(0xffffffffu, v, o);
        if (lane >= o) v += t;
    }
    if (lane == 31) warpsum[w] = v;
    __syncthreads();
    if (w == 0) {
        int ws = warpsum[lane];
        #pragma unroll
        for (int o = 1; o < 32; o <<= 1) {
            int t = __shfl_up_sync(0xffffffffu, ws, o);
            if (lane >= o) ws += t;
        }
        warpsum[lane] = ws;
    }
    __syncthreads();
    int prefix = (v - s) + (w > 0 ? warpsum[w - 1] : 0);   // exclusive base of this thread's chunk

    int run = prefix;
    for (int k = 0; k < CH; k++) {
        int idx = start + k;
        if (idx < N_NODES) {
            g_base[idx] = run;
            g_cursor[idx] = run;
            run += g_cnt[idx];
        }
    }
}

// ---------------------------------------------------------------------------
// K4: place edges into dst-sorted buckets (int atomics only)
// ---------------------------------------------------------------------------
__global__ void __launch_bounds__(256) place_kernel(const int* __restrict__ ei) {
    int e = blockIdx.x * 256 + threadIdx.x;
    int d = ei[N_EDGES + e];
    int pos = atomicAdd(&g_cursor[d], 1);
    g_psrc[pos] = ei[e];
    g_pe[pos] = e;
}

// ---------------------------------------------------------------------------
// K5: aggregate. 2 threads per node (warp-parity halves). For each edge in
// the node's bucket: h = xw1[src] + ef@W1e; acc += relu(h). One plain store.
// ---------------------------------------------------------------------------
__global__ void __launch_bounds__(256) aggregate_kernel(
        const float* __restrict__ ef,
        const float* __restrict__ W1) {
    __shared__ ulonglong2 sW1e[16 * 16];  // W1 rows 64..79
    int tid = threadIdx.x;
    sW1e[tid] = reinterpret_cast<const ulonglong2*>(W1)[1024 + tid];
    __syncthreads();

    int warp = tid >> 5, lane = tid & 31;
    int h = warp & 1, g = warp >> 1;
    int n = blockIdx.x * 128 + g * 32 + lane;
    if (n >= N_NODES) return;

    int deg  = g_cnt[n];
    int base = g_base[n];

    float acc[32];
    #pragma unroll
    for (int j = 0; j < 32; j++) acc[j] = 0.0f;

    for (int i = 0; i < deg; i++) {
        int pos = base + i;
        int src = g_psrc[pos];
        int e   = g_pe[pos];

        u64 hh[16];
        const ulonglong2* xr = reinterpret_cast<const ulonglong2*>(
            g_xw1 + (size_t)src * 64 + h * 32);
        #pragma unroll
        for (int j = 0; j < 8; j++) { ulonglong2 v = xr[j]; hh[2*j] = v.x; hh[2*j+1] = v.y; }

        float efr[16];
        const float4* er = reinterpret_cast<const float4*>(ef + (size_t)e * 16);
        #pragma unroll
        for (int j = 0; j < 4; j++) {
            float4 f = er[j];
            efr[4*j] = f.x; efr[4*j+1] = f.y; efr[4*j+2] = f.z; efr[4*j+3] = f.w;
        }

        #pragma unroll
        for (int ii = 0; ii < 16; ii++) {
            u64 a = pack2(efr[ii]);
            #pragma unroll
            for (int j = 0; j < 8; j++) {
                ulonglong2 w = sW1e[ii * 16 + h * 8 + j];
                ffma2(hh[2*j], a, w.x);
                ffma2(hh[2*j+1], a, w.y);
            }
        }
        #pragma unroll
        for (int j = 0; j < 16; j++) {
            float lo, hi; unpack2(hh[j], lo, hi);
            acc[2*j]   += fmaxf(lo, 0.0f);
            acc[2*j+1] += fmaxf(hi, 0.0f);
        }
    }

    float4* o = reinterpret_cast<float4*>(g_agg + (size_t)n * 64 + h * 32);
    #pragma unroll
    for (int j = 0; j < 8; j++)
        o[j] = make_float4(acc[4*j], acc[4*j+1], acc[4*j+2], acc[4*j+3]);
}

// ---------------------------------------------------------------------------
// K6: g_xw1[n] = (g_agg[n] @ W2) * inv + b2 * (cnt*inv)
// ---------------------------------------------------------------------------
__global__ void __launch_bounds__(128) nodeA_kernel(
        const float* __restrict__ W2,
        const float* __restrict__ b2) {
    __shared__ ulonglong2 sW[64 * 16];
    __shared__ float sb[64];
    int tid = threadIdx.x;
    const ulonglong2* W2v = reinterpret_cast<const ulonglong2*>(W2);
    for (int idx = tid; idx < 64 * 16; idx += 128) sW[idx] = W2v[idx];
    if (tid < 64) sb[tid] = b2[tid];
    __syncthreads();

    int n = blockIdx.x * 128 + tid;
    if (n >= N_NODES) return;

    float cnt = (float)g_cnt[n];
    float inv = 1.0f / (cnt + 1e-8f);
    float bs  = cnt * inv;

    u64 acc[32];
    #pragma unroll
    for (int j = 0; j < 32; j++) acc[j] = 0ull;

    const float4* ar = reinterpret_cast<const float4*>(g_agg + (size_t)n * 64);
    #pragma unroll 1
    for (int c = 0; c < 2; c++) {
        float v[32];
        #pragma unroll
        for (int j = 0; j < 8; j++) {
            float4 f = ar[c * 8 + j];
            v[4*j] = f.x; v[4*j+1] = f.y; v[4*j+2] = f.z; v[4*j+3] = f.w;
        }
        #pragma unroll
        for (int i = 0; i < 32; i++) {
            u64 a = pack2(v[i]);
            #pragma unroll
            for (int j = 0; j < 16; j++) {
                ulonglong2 w = sW[(c * 32 + i) * 16 + j];
                ffma2(acc[2*j], a, w.x);
                ffma2(acc[2*j+1], a, w.y);
            }
        }
    }
    float4* o = reinterpret_cast<float4*>(g_xw1 + (size_t)n * 64);
    #pragma unroll
    for (int j = 0; j < 16; j++) {
        float4 v;
        unpack2(acc[2*j],   v.x, v.y);
        unpack2(acc[2*j+1], v.z, v.w);
        v.x = v.x * inv + sb[4*j]   * bs;
        v.y = v.y * inv + sb[4*j+1] * bs;
        v.z = v.z * inv + sb[4*j+2] * bs;
        v.w = v.w * inv + sb[4*j+3] * bs;
        o[j] = v;
    }
}

// ---------------------------------------------------------------------------
// K7: y = relu([x, agg_mean] @ W3 + b3) + x ; LayerNorm -> out
// ---------------------------------------------------------------------------
__global__ void __launch_bounds__(128) nodeB_kernel(
        const float* __restrict__ x,
        const float* __restrict__ W3,
        const float* __restrict__ b3,
        const float* __restrict__ gamma,
        const float* __restrict__ beta,
        float* __restrict__ out) {
    __shared__ ulonglong2 sW[128 * 16];  // 32 KB
    __shared__ ulonglong2 sb[16];
    __shared__ float sg[64], sbt[64];
    int tid = threadIdx.x;
    const ulonglong2* W3v = reinterpret_cast<const ulonglong2*>(W3);
    for (int idx = tid; idx < 128 * 16; idx += 128) sW[idx] = W3v[idx];
    if (tid < 16) sb[tid] = reinterpret_cast<const ulonglong2*>(b3)[tid];
    if (tid < 64) { sg[tid] = gamma[tid]; sbt[tid] = beta[tid]; }
    __syncthreads();

    int n = blockIdx.x * 128 + tid;
    if (n >= N_NODES) return;

    u64 acc[32];
    #pragma unroll
    for (int j = 0; j < 16; j++) { ulonglong2 v = sb[j]; acc[2*j] = v.x; acc[2*j+1] = v.y; }

    const float4* xr = reinterpret_cast<const float4*>(x + (size_t)n * 64);
    const float4* ar = reinterpret_cast<const float4*>(g_xw1 + (size_t)n * 64);

    #pragma unroll 1
    for (int c = 0; c < 4; c++) {
        const float4* p = (c < 2) ? (xr + (c & 1) * 8) : (ar + (c & 1) * 8);
        float v[32];
        #pragma unroll
        for (int j = 0; j < 8; j++) {
            float4 f = p[j];
            v[4*j] = f.x; v[4*j+1] = f.y; v[4*j+2] = f.z; v[4*j+3] = f.w;
        }
        #pragma unroll
        for (int i = 0; i < 32; i++) {
            u64 a = pack2(v[i]);
            #pragma unroll
            for (int j = 0; j < 16; j++) {
                ulonglong2 w = sW[(c * 32 + i) * 16 + j];
                ffma2(acc[2*j], a, w.x);
                ffma2(acc[2*j+1], a, w.y);
            }
        }
    }

    float u[64];
    #pragma unroll
    for (int j = 0; j < 16; j++) {
        float4 f = xr[j];
        float a0, a1, a2, a3;
        unpack2(acc[2*j],   a0, a1);
        unpack2(acc[2*j+1], a2, a3);
        u[4*j]   = fmaxf(a0, 0.0f) + f.x;
        u[4*j+1] = fmaxf(a1, 0.0f) + f.y;
        u[4*j+2] = fmaxf(a2, 0.0f) + f.z;
        u[4*j+3] = fmaxf(a3, 0.0f) + f.w;
    }

    float s = 0.0f, ss = 0.0f;
    #pragma unroll
    for (int j = 0; j < 64; j++) { s += u[j]; ss = fmaf(u[j], u[j], ss); }
    float mu  = s * (1.0f / 64.0f);
    float var = ss * (1.0f / 64.0f) - mu * mu;
    float r   = rsqrtf(var + 1e-5f);

    float4* o = reinterpret_cast<float4*>(out + (size_t)n * 64);
    #pragma unroll
    for (int j = 0; j < 16; j++) {
        float4 v;
        v.x = (u[4*j]   - mu) * r * sg[4*j]   + sbt[4*j];
        v.y = (u[4*j+1] - mu) * r * sg[4*j+1] + sbt[4*j+1];
        v.z = (u[4*j+2] - mu) * r * sg[4*j+2] + sbt[4*j+2];
        v.w = (u[4*j+3] - mu) * r * sg[4*j+3] + sbt[4*j+3];
        o[j] = v;
    }
}

// ---------------------------------------------------------------------------
extern "C" void kernel_launch(void* const* d_in, const int* in_sizes, int n_in,
                              void* d_out, int out_size) {
    const float* x     = (const float*)d_in[0];
    const int*   ei    = (const int*)  d_in[1];
    const float* ef    = (const float*)d_in[2];
    const float* W1    = (const float*)d_in[3];
    const float* b1    = (const float*)d_in[4];
    const float* W2    = (const float*)d_in[5];
    const float* b2    = (const float*)d_in[6];
    const float* W3    = (const float*)d_in[7];
    const float* b3    = (const float*)d_in[8];
    const float* gamma = (const float*)d_in[9];
    const float* beta  = (const float*)d_in[10];
    float* out = (float*)d_out;

    (void)in_sizes; (void)n_in; (void)out_size;

    const int nb128 = (N_NODES + 127) / 128;

    precompute_kernel<<<nb128, 128>>>(x, W1, b1);
    count_kernel<<<N_EDGES / 256, 256>>>(ei);
    scan_kernel<<<1, 1024>>>();
    place_kernel<<<N_EDGES / 256, 256>>>(ei);
    aggregate_kernel<<<nb128, 256>>>(ef, W1);
    nodeA_kernel<<<nb128, 128>>>(W2, b2);
    nodeB_kernel<<<nb128, 128>>>(x, W3, b3, gamma, beta, out);
}

// round 6
// speedup vs baseline: 2.9684x; 2.9684x over previous
#include <cuda_runtime.h>
#include <cstdint>
#include <cstddef>

#define N_NODES 50000
#define N_EDGES 800000

// Scratch (device globals: no runtime allocation allowed)
__device__ __align__(16) float g_xw1[N_NODES * 64];   // x@W1[:64]+b1
__device__ __align__(16) float g_agg[N_NODES * 64];   // per-node sum of relu(h)
__device__ __align__(16) float g_msg[(size_t)N_EDGES * 64];  // dst-sorted messages (204.8 MB)
__device__ __align__(16) float g_wc[64 * 64];         // W2 @ W3[64:128,:]
__device__ float g_bc[64];                            // b2 @ W3[64:128,:]
__device__ int g_cnt[N_NODES];
__device__ int g_base[N_NODES];
__device__ int g_cursor[N_NODES];

typedef unsigned long long u64;

__device__ __forceinline__ u64 pack2(float v) {
    u64 r; asm("mov.b64 %0, {%1, %1};" : "=l"(r) : "f"(v)); return r;
}
__device__ __forceinline__ u64 pack2f(float lo, float hi) {
    u64 r; asm("mov.b64 %0, {%1, %2};" : "=l"(r) : "f"(lo), "f"(hi)); return r;
}
__device__ __forceinline__ void unpack2(u64 v, float &lo, float &hi) {
    asm("mov.b64 {%0, %1}, %2;" : "=f"(lo), "=f"(hi) : "l"(v));
}
__device__ __forceinline__ void ffma2(u64 &d, u64 a, u64 b) {
    asm("fma.rn.f32x2 %0, %1, %2, %0;" : "+l"(d) : "l"(a), "l"(b));
}

// ---------------------------------------------------------------------------
// K0: Wc = W2 @ W3[64:128,:],  bc = b2 @ W3[64:128,:]
// grid 64 (block i = Wc row), 64 threads (j). W3 reads coalesced across j.
// ---------------------------------------------------------------------------
__global__ void __launch_bounds__(64) prep_kernel(
        const float* __restrict__ W2,
        const float* __restrict__ W3,
        const float* __restrict__ b2) {
    __shared__ float sw2[64];
    int i = blockIdx.x, j = threadIdx.x;
    sw2[j] = W2[i * 64 + j];
    __syncthreads();
    float acc = 0.0f;
    #pragma unroll 8
    for (int k = 0; k < 64; k++)
        acc = fmaf(sw2[k], W3[(64 + k) * 64 + j], acc);
    g_wc[i * 64 + j] = acc;
    if (i == 0) {
        float accb = 0.0f;
        for (int k = 0; k < 64; k++)
            accb = fmaf(b2[k], W3[(64 + k) * 64 + j], accb);
        g_bc[j] = accb;
    }
}

// ---------------------------------------------------------------------------
// K1: g_xw1[n] = x[n] @ W1[0:64,:] + b1 ; zero g_cnt.
// ---------------------------------------------------------------------------
__global__ void __launch_bounds__(128) precompute_kernel(
        const float* __restrict__ x,
        const float* __restrict__ W1,
        const float* __restrict__ b1) {
    __shared__ ulonglong2 sW[64 * 16];   // 16 KB
    __shared__ ulonglong2 sb[16];
    int tid = threadIdx.x;
    const ulonglong2* W1v = reinterpret_cast<const ulonglong2*>(W1);
    for (int idx = tid; idx < 64 * 16; idx += 128) sW[idx] = W1v[idx];
    if (tid < 16) sb[tid] = reinterpret_cast<const ulonglong2*>(b1)[tid];
    __syncthreads();

    int n = blockIdx.x * 128 + tid;
    if (n >= N_NODES) return;

    u64 acc[32];
    #pragma unroll
    for (int j = 0; j < 16; j++) { ulonglong2 v = sb[j]; acc[2*j] = v.x; acc[2*j+1] = v.y; }

    const float4* xr = reinterpret_cast<const float4*>(x + (size_t)n * 64);
    #pragma unroll 1
    for (int c = 0; c < 2; c++) {
        float v[32];
        #pragma unroll
        for (int j = 0; j < 8; j++) {
            float4 f = xr[c * 8 + j];
            v[4*j] = f.x; v[4*j+1] = f.y; v[4*j+2] = f.z; v[4*j+3] = f.w;
        }
        #pragma unroll
        for (int i = 0; i < 32; i++) {
            u64 a = pack2(v[i]);
            #pragma unroll
            for (int j = 0; j < 16; j++) {
                ulonglong2 w = sW[(c * 32 + i) * 16 + j];
                ffma2(acc[2*j], a, w.x);
                ffma2(acc[2*j+1], a, w.y);
            }
        }
    }
    ulonglong2* o = reinterpret_cast<ulonglong2*>(g_xw1 + (size_t)n * 64);
    #pragma unroll
    for (int j = 0; j < 16; j++) {
        ulonglong2 v; v.x = acc[2*j]; v.y = acc[2*j+1]; o[j] = v;
    }
    g_cnt[n] = 0;
}

// ---------------------------------------------------------------------------
// K2: count in-degrees (int atomics, L2-resident)
// ---------------------------------------------------------------------------
__global__ void __launch_bounds__(256) count_kernel(const int* __restrict__ ei) {
    int e = blockIdx.x * 256 + threadIdx.x;   // N_EDGES % 256 == 0
    atomicAdd(&g_cnt[ei[N_EDGES + e]], 1);
}

// ---------------------------------------------------------------------------
// K3: exclusive prefix sum of g_cnt -> g_base, g_cursor. One block.
// ---------------------------------------------------------------------------
__global__ void __launch_bounds__(1024) scan_kernel() {
    __shared__ int warpsum[32];
    int tid = threadIdx.x;
    const int CH = (N_NODES + 1023) / 1024;   // 49
    int start = tid * CH;

    int s = 0;
    for (int k = 0; k < CH; k++) {
        int idx = start + k;
        if (idx < N_NODES) s += g_cnt[idx];
    }
    int lane = tid & 31, w = tid >> 5;
    int v = s;
    #pragma unroll
    for (int o = 1; o < 32; o <<= 1) {
        int t = __shfl_up_sync(0xffffffffu, v, o);
        if (lane >= o) v += t;
    }
    if (lane == 31) warpsum[w] = v;
    __syncthreads();
    if (w == 0) {
        int ws = warpsum[lane];
        #pragma unroll
        for (int o = 1; o < 32; o <<= 1) {
            int t = __shfl_up_sync(0xffffffffu, ws, o);
            if (lane >= o) ws += t;
        }
        warpsum[lane] = ws;
    }
    __syncthreads();
    int prefix = (v - s) + (w > 0 ? warpsum[w - 1] : 0);

    int run = prefix;
    for (int k = 0; k < CH; k++) {
        int idx = start + k;
        if (idx < N_NODES) {
            g_base[idx] = run;
            g_cursor[idx] = run;
            run += g_cnt[idx];
        }
    }
}

// ---------------------------------------------------------------------------
// K4: messages, edge-parallel. h = relu(xw1[src] + ef@W1e) -> g_msg[pos]
// (pos = slot in dst-sorted order; plain STG.128, no float atomics)
// ---------------------------------------------------------------------------
__global__ void __launch_bounds__(256) msg_kernel(
        const int*   __restrict__ ei,
        const float* __restrict__ ef,
        const float* __restrict__ W1) {
    __shared__ ulonglong2 sW1e[16 * 16];  // W1 rows 64..79, 4 KB
    int tid = threadIdx.x;
    sW1e[tid] = reinterpret_cast<const ulonglong2*>(W1)[1024 + tid];
    __syncthreads();

    int e = blockIdx.x * 256 + tid;
    int s = ei[e];
    int d = ei[N_EDGES + e];

    u64 acc[32];
    const ulonglong2* xr = reinterpret_cast<const ulonglong2*>(g_xw1 + (size_t)s * 64);
    #pragma unroll
    for (int j = 0; j < 16; j++) { ulonglong2 v = xr[j]; acc[2*j] = v.x; acc[2*j+1] = v.y; }

    float efr[16];
    const float4* er = reinterpret_cast<const float4*>(ef + (size_t)e * 16);
    #pragma unroll
    for (int j = 0; j < 4; j++) {
        float4 f = er[j];
        efr[4*j] = f.x; efr[4*j+1] = f.y; efr[4*j+2] = f.z; efr[4*j+3] = f.w;
    }

    #pragma unroll
    for (int i = 0; i < 16; i++) {
        u64 a = pack2(efr[i]);
        #pragma unroll
        for (int j = 0; j < 16; j++) {
            ulonglong2 w = sW1e[i * 16 + j];
            ffma2(acc[2*j], a, w.x);
            ffma2(acc[2*j+1], a, w.y);
        }
    }

    int pos = atomicAdd(&g_cursor[d], 1);
    float4* o = reinterpret_cast<float4*>(g_msg + (size_t)pos * 64);
    #pragma unroll
    for (int j = 0; j < 16; j++) {
        float4 v;
        unpack2(acc[2*j],   v.x, v.y);
        unpack2(acc[2*j+1], v.z, v.w);
        v.x = fmaxf(v.x, 0.f); v.y = fmaxf(v.y, 0.f);
        v.z = fmaxf(v.z, 0.f); v.w = fmaxf(v.w, 0.f);
        o[j] = v;
    }
}

// ---------------------------------------------------------------------------
// K5: segmented sum. Warp per node; lane owns 2 columns (float2).
// Contiguous coalesced reads, independent iterations (high MLP).
// ---------------------------------------------------------------------------
__global__ void __launch_bounds__(256) segsum_kernel() {
    int tid  = threadIdx.x;
    int warp = tid >> 5, lane = tid & 31;
    int n = blockIdx.x * 8 + warp;   // 6250 * 8 = 50000 exactly
    if (n >= N_NODES) return;

    int deg  = g_cnt[n];
    int base = g_base[n];

    const float2* m = reinterpret_cast<const float2*>(g_msg) + (size_t)base * 32 + lane;
    float2 a0 = make_float2(0.f, 0.f), a1 = make_float2(0.f, 0.f);
    float2 a2 = make_float2(0.f, 0.f), a3 = make_float2(0.f, 0.f);
    int i = 0;
    for (; i + 4 <= deg; i += 4) {
        float2 r0 = m[(size_t)(i+0) * 32];
        float2 r1 = m[(size_t)(i+1) * 32];
        float2 r2 = m[(size_t)(i+2) * 32];
        float2 r3 = m[(size_t)(i+3) * 32];
        a0.x += r0.x; a0.y += r0.y;
        a1.x += r1.x; a1.y += r1.y;
        a2.x += r2.x; a2.y += r2.y;
        a3.x += r3.x; a3.y += r3.y;
    }
    for (; i < deg; i++) {
        float2 r = m[(size_t)i * 32];
        a0.x += r.x; a0.y += r.y;
    }
    a0.x += a1.x + a2.x + a3.x;
    a0.y += a1.y + a2.y + a3.y;

    reinterpret_cast<float2*>(g_agg + (size_t)n * 64)[lane] = a0;
}

// ---------------------------------------------------------------------------
// K6: fused update+LN (nodeA folded in):
//   acc = x@W3[0:64] + (aggsum*inv)@Wc + b3 + bc*(cnt*inv)
//   y = relu(acc) + x ; LayerNorm -> out
// ---------------------------------------------------------------------------
__global__ void __launch_bounds__(128) nodeB_kernel(
        const float* __restrict__ x,
        const float* __restrict__ W3,
        const float* __restrict__ b3,
        const float* __restrict__ gamma,
        const float* __restrict__ beta,
        float* __restrict__ out) {
    __shared__ ulonglong2 sW[128 * 16];  // 32 KB: rows 0..63 = W3 top, 64..127 = Wc
    __shared__ float sb3[64], sbc[64], sg[64], sbt[64];
    int tid = threadIdx.x;
    const ulonglong2* W3v = reinterpret_cast<const ulonglong2*>(W3);
    const ulonglong2* Wcv = reinterpret_cast<const ulonglong2*>(g_wc);
    for (int idx = tid; idx < 64 * 16; idx += 128) {
        sW[idx] = W3v[idx];
        sW[64 * 16 + idx] = Wcv[idx];
    }
    if (tid < 64) { sb3[tid] = b3[tid]; sbc[tid] = g_bc[tid]; sg[tid] = gamma[tid]; sbt[tid] = beta[tid]; }
    __syncthreads();

    int n = blockIdx.x * 128 + tid;
    if (n >= N_NODES) return;

    float cnt = (float)g_cnt[n];
    float inv = 1.0f / (cnt + 1e-8f);
    float bs  = cnt * inv;

    u64 acc[32];
    #pragma unroll
    for (int j = 0; j < 32; j++)
        acc[j] = pack2f(fmaf(bs, sbc[2*j], sb3[2*j]), fmaf(bs, sbc[2*j+1], sb3[2*j+1]));

    const float4* xr = reinterpret_cast<const float4*>(x + (size_t)n * 64);
    const float4* ar = reinterpret_cast<const float4*>(g_agg + (size_t)n * 64);

    #pragma unroll 1
    for (int c = 0; c < 4; c++) {
        bool isx = (c < 2);
        const float4* p = isx ? (xr + (c & 1) * 8) : (ar + (c & 1) * 8);
        float v[32];
        #pragma unroll
        for (int j = 0; j < 8; j++) {
            float4 f = p[j];
            v[4*j] = f.x; v[4*j+1] = f.y; v[4*j+2] = f.z; v[4*j+3] = f.w;
        }
        if (!isx) {
            #pragma unroll
            for (int j = 0; j < 32; j++) v[j] *= inv;
        }
        #pragma unroll
        for (int i = 0; i < 32; i++) {
            u64 a = pack2(v[i]);
            #pragma unroll
            for (int j = 0; j < 16; j++) {
                ulonglong2 w = sW[(c * 32 + i) * 16 + j];
                ffma2(acc[2*j], a, w.x);
                ffma2(acc[2*j+1], a, w.y);
            }
        }
    }

    float u[64];
    #pragma unroll
    for (int j = 0; j < 16; j++) {
        float4 f = xr[j];
        float a0, a1, a2, a3;
        unpack2(acc[2*j],   a0, a1);
        unpack2(acc[2*j+1], a2, a3);
        u[4*j]   = fmaxf(a0, 0.0f) + f.x;
        u[4*j+1] = fmaxf(a1, 0.0f) + f.y;
        u[4*j+2] = fmaxf(a2, 0.0f) + f.z;
        u[4*j+3] = fmaxf(a3, 0.0f) + f.w;
    }

    float s = 0.0f, ss = 0.0f;
    #pragma unroll
    for (int j = 0; j < 64; j++) { s += u[j]; ss = fmaf(u[j], u[j], ss); }
    float mu  = s * (1.0f / 64.0f);
    float var = ss * (1.0f / 64.0f) - mu * mu;
    float r   = rsqrtf(var + 1e-5f);

    float4* o = reinterpret_cast<float4*>(out + (size_t)n * 64);
    #pragma unroll
    for (int j = 0; j < 16; j++) {
        float4 v;
        v.x = (u[4*j]   - mu) * r * sg[4*j]   + sbt[4*j];
        v.y = (u[4*j+1] - mu) * r * sg[4*j+1] + sbt[4*j+1];
        v.z = (u[4*j+2] - mu) * r * sg[4*j+2] + sbt[4*j+2];
        v.w = (u[4*j+3] - mu) * r * sg[4*j+3] + sbt[4*j+3];
        o[j] = v;
    }
}

// ---------------------------------------------------------------------------
extern "C" void kernel_launch(void* const* d_in, const int* in_sizes, int n_in,
                              void* d_out, int out_size) {
    const float* x     = (const float*)d_in[0];
    const int*   ei    = (const int*)  d_in[1];
    const float* ef    = (const float*)d_in[2];
    const float* W1    = (const float*)d_in[3];
    const float* b1    = (const float*)d_in[4];
    const float* W2    = (const float*)d_in[5];
    const float* b2    = (const float*)d_in[6];
    const float* W3    = (const float*)d_in[7];
    const float* b3    = (const float*)d_in[8];
    const float* gamma = (const float*)d_in[9];
    const float* beta  = (const float*)d_in[10];
    float* out = (float*)d_out;

    (void)in_sizes; (void)n_in; (void)out_size;

    const int nb128 = (N_NODES + 127) / 128;

    prep_kernel<<<64, 64>>>(W2, W3, b2);
    precompute_kernel<<<nb128, 128>>>(x, W1, b1);
    count_kernel<<<N_EDGES / 256, 256>>>(ei);
    scan_kernel<<<1, 1024>>>();
    msg_kernel<<<N_EDGES / 256, 256>>>(ei, ef, W1);
    segsum_kernel<<<(N_NODES + 7) / 8, 256>>>();
    nodeB_kernel<<<nb128, 128>>>(x, W3, b3, gamma, beta, out);
}

// round 7
// speedup vs baseline: 4.7355x; 1.5953x over previous
#include <cuda_runtime.h>
#include <cstdint>
#include <cstddef>

#define N_NODES 50000
#define N_EDGES 800000
#define NB_SCAN 196          // ceil(50000/256)

// Scratch (device globals: no runtime allocation allowed)
__device__ __align__(16) float g_xw1[N_NODES * 64];   // x@W1[:64]+b1
__device__ __align__(16) float g_agg[N_NODES * 64];   // per-node sum of relu(h)
__device__ __align__(16) float g_wc[64 * 64];         // W2 @ W3[64:128,:]
__device__ float g_bc[64];                            // b2 @ W3[64:128,:]
__device__ int g_cnt[N_NODES];
__device__ int g_base[N_NODES];
__device__ int g_cursor[N_NODES];
__device__ int g_psrc[N_EDGES];                       // src, dst-sorted
__device__ int g_pe[N_EDGES];                         // edge id, dst-sorted
__device__ int g_pdst[N_EDGES];                       // dst, dst-sorted
__device__ int g_bsum[NB_SCAN];
__device__ int g_boff[256];

typedef unsigned long long u64;

__device__ __forceinline__ u64 pack2(float v) {
    u64 r; asm("mov.b64 %0, {%1, %1};" : "=l"(r) : "f"(v)); return r;
}
__device__ __forceinline__ u64 pack2f(float lo, float hi) {
    u64 r; asm("mov.b64 %0, {%1, %2};" : "=l"(r) : "f"(lo), "f"(hi)); return r;
}
__device__ __forceinline__ void unpack2(u64 v, float &lo, float &hi) {
    asm("mov.b64 {%0, %1}, %2;" : "=f"(lo), "=f"(hi) : "l"(v));
}
__device__ __forceinline__ void ffma2(u64 &d, u64 a, u64 b) {
    asm("fma.rn.f32x2 %0, %1, %2, %0;" : "+l"(d) : "l"(a), "l"(b));
}
__device__ __forceinline__ void red_add_v2(float* addr, float vx, float vy) {
    asm volatile("red.global.add.v2.f32 [%0], {%1, %2};"
                 :: "l"(addr), "f"(vx), "f"(vy) : "memory");
}

// ---------------------------------------------------------------------------
// K0: Wc = W2 @ W3[64:128,:],  bc = b2 @ W3[64:128,:]
// ---------------------------------------------------------------------------
__global__ void __launch_bounds__(64) prep_kernel(
        const float* __restrict__ W2,
        const float* __restrict__ W3,
        const float* __restrict__ b2) {
    __shared__ float sw2[64];
    int i = blockIdx.x, j = threadIdx.x;
    sw2[j] = W2[i * 64 + j];
    __syncthreads();
    float acc = 0.0f;
    #pragma unroll 8
    for (int k = 0; k < 64; k++)
        acc = fmaf(sw2[k], W3[(64 + k) * 64 + j], acc);
    g_wc[i * 64 + j] = acc;
    if (i == 0) {
        float accb = 0.0f;
        for (int k = 0; k < 64; k++)
            accb = fmaf(b2[k], W3[(64 + k) * 64 + j], accb);
        g_bc[j] = accb;
    }
}

// ---------------------------------------------------------------------------
// K1: g_xw1[n] = x[n] @ W1[0:64,:] + b1 ; zero g_agg row, g_cnt.
// ---------------------------------------------------------------------------
__global__ void __launch_bounds__(128) precompute_kernel(
        const float* __restrict__ x,
        const float* __restrict__ W1,
        const float* __restrict__ b1) {
    __shared__ ulonglong2 sW[64 * 16];   // 16 KB
    __shared__ ulonglong2 sb[16];
    int tid = threadIdx.x;
    const ulonglong2* W1v = reinterpret_cast<const ulonglong2*>(W1);
    for (int idx = tid; idx < 64 * 16; idx += 128) sW[idx] = W1v[idx];
    if (tid < 16) sb[tid] = reinterpret_cast<const ulonglong2*>(b1)[tid];
    __syncthreads();

    int n = blockIdx.x * 128 + tid;
    if (n >= N_NODES) return;

    u64 acc[32];
    #pragma unroll
    for (int j = 0; j < 16; j++) { ulonglong2 v = sb[j]; acc[2*j] = v.x; acc[2*j+1] = v.y; }

    const float4* xr = reinterpret_cast<const float4*>(x + (size_t)n * 64);
    #pragma unroll 1
    for (int c = 0; c < 2; c++) {
        float v[32];
        #pragma unroll
        for (int j = 0; j < 8; j++) {
            float4 f = xr[c * 8 + j];
            v[4*j] = f.x; v[4*j+1] = f.y; v[4*j+2] = f.z; v[4*j+3] = f.w;
        }
        #pragma unroll
        for (int i = 0; i < 32; i++) {
            u64 a = pack2(v[i]);
            #pragma unroll
            for (int j = 0; j < 16; j++) {
                ulonglong2 w = sW[(c * 32 + i) * 16 + j];
                ffma2(acc[2*j], a, w.x);
                ffma2(acc[2*j+1], a, w.y);
            }
        }
    }
    ulonglong2* o = reinterpret_cast<ulonglong2*>(g_xw1 + (size_t)n * 64);
    float4* az = reinterpret_cast<float4*>(g_agg + (size_t)n * 64);
    float4 z = make_float4(0.f, 0.f, 0.f, 0.f);
    #pragma unroll
    for (int j = 0; j < 16; j++) {
        ulonglong2 v; v.x = acc[2*j]; v.y = acc[2*j+1]; o[j] = v;
        az[j] = z;
    }
    g_cnt[n] = 0;
}

// ---------------------------------------------------------------------------
// K2: count in-degrees
// ---------------------------------------------------------------------------
__global__ void __launch_bounds__(256) count_kernel(const int* __restrict__ ei) {
    int e = blockIdx.x * 256 + threadIdx.x;
    atomicAdd(&g_cnt[ei[N_EDGES + e]], 1);
}

// ---------------------------------------------------------------------------
// K3a/b/c: two-level parallel exclusive scan of g_cnt -> g_base, g_cursor
// ---------------------------------------------------------------------------
__global__ void __launch_bounds__(256) scanA_kernel() {
    int b = blockIdx.x, tid = threadIdx.x;
    int idx = b * 256 + tid;
    int v = (idx < N_NODES) ? g_cnt[idx] : 0;
    __shared__ int ws[8];
    #pragma unroll
    for (int o = 16; o > 0; o >>= 1) v += __shfl_down_sync(0xffffffffu, v, o);
    if ((tid & 31) == 0) ws[tid >> 5] = v;
    __syncthreads();
    if (tid == 0) {
        int s = 0;
        #pragma unroll
        for (int k = 0; k < 8; k++) s += ws[k];
        g_bsum[b] = s;
    }
}

__global__ void __launch_bounds__(256) scanB_kernel() {
    int tid = threadIdx.x, lane = tid & 31, w = tid >> 5;
    int v = (tid < NB_SCAN) ? g_bsum[tid] : 0;
    int inc = v;
    __shared__ int ws[8];
    #pragma unroll
    for (int o = 1; o < 32; o <<= 1) {
        int t = __shfl_up_sync(0xffffffffu, inc, o);
        if (lane >= o) inc += t;
    }
    if (lane == 31) ws[w] = inc;
    __syncthreads();
    int off = 0;
    #pragma unroll
    for (int k = 0; k < 8; k++) off += (k < w) ? ws[k] : 0;
    g_boff[tid] = off + inc - v;   // exclusive
}

__global__ void __launch_bounds__(256) scanC_kernel() {
    int b = blockIdx.x, tid = threadIdx.x, lane = tid & 31, w = tid >> 5;
    int idx = b * 256 + tid;
    int c = (idx < N_NODES) ? g_cnt[idx] : 0;
    int inc = c;
    __shared__ int ws[8];
    #pragma unroll
    for (int o = 1; o < 32; o <<= 1) {
        int t = __shfl_up_sync(0xffffffffu, inc, o);
        if (lane >= o) inc += t;
    }
    if (lane == 31) ws[w] = inc;
    __syncthreads();
    int off = g_boff[b];
    #pragma unroll
    for (int k = 0; k < 8; k++) off += (k < w) ? ws[k] : 0;
    int base = off + inc - c;
    if (idx < N_NODES) { g_base[idx] = base; g_cursor[idx] = base; }
}

// ---------------------------------------------------------------------------
// K4: place edges into dst-sorted buckets
// ---------------------------------------------------------------------------
__global__ void __launch_bounds__(256) place_kernel(const int* __restrict__ ei) {
    int e = blockIdx.x * 256 + threadIdx.x;
    int d = ei[N_EDGES + e];
    int pos = atomicAdd(&g_cursor[d], 1);
    g_psrc[pos] = ei[e];
    g_pe[pos] = e;
    g_pdst[pos] = d;
}

// ---------------------------------------------------------------------------
// K5: aggregate over sorted slots. Block = 128 slots.
//   m = relu(xw1[src] + ef@W1e)  -> smem
//   segment (equal-dst run) reduce -> red.add.v2 into g_agg
// ---------------------------------------------------------------------------
__global__ void __launch_bounds__(128) aggregate_kernel(
        const float* __restrict__ ef,
        const float* __restrict__ W1) {
    __shared__ ulonglong2 sW1e[16 * 16];          // 4 KB
    __shared__ float sm[128 * 66];                // 33 KB, stride 66 (bank-safe)
    __shared__ int sdst[128];
    __shared__ int sheads[129];
    __shared__ int snseg;

    int tid = threadIdx.x;
    sW1e[tid * 2]     = reinterpret_cast<const ulonglong2*>(W1)[1024 + tid * 2];
    sW1e[tid * 2 + 1] = reinterpret_cast<const ulonglong2*>(W1)[1024 + tid * 2 + 1];
    if (tid == 0) snseg = 0;

    int slot = blockIdx.x * 128 + tid;            // N_EDGES % 128 == 0, all valid
    int src = g_psrc[slot];
    int e   = g_pe[slot];
    int d   = g_pdst[slot];
    sdst[tid] = d;

    // message compute
    u64 acc[32];
    const ulonglong2* xr = reinterpret_cast<const ulonglong2*>(g_xw1 + (size_t)src * 64);
    #pragma unroll
    for (int j = 0; j < 16; j++) { ulonglong2 v = xr[j]; acc[2*j] = v.x; acc[2*j+1] = v.y; }

    float efr[16];
    const float4* er = reinterpret_cast<const float4*>(ef + (size_t)e * 16);
    #pragma unroll
    for (int j = 0; j < 4; j++) {
        float4 f = er[j];
        efr[4*j] = f.x; efr[4*j+1] = f.y; efr[4*j+2] = f.z; efr[4*j+3] = f.w;
    }
    __syncthreads();   // sW1e ready (also covers sdst/snseg)

    #pragma unroll
    for (int i = 0; i < 16; i++) {
        u64 a = pack2(efr[i]);
        #pragma unroll
        for (int j = 0; j < 16; j++) {
            ulonglong2 w = sW1e[i * 16 + j];
            ffma2(acc[2*j], a, w.x);
            ffma2(acc[2*j+1], a, w.y);
        }
    }

    // relu -> smem (stride-66 rows, float2 cells)
    float2* myrow = reinterpret_cast<float2*>(sm + tid * 66);
    #pragma unroll
    for (int j = 0; j < 32; j++) {
        float lo, hi; unpack2(acc[j], lo, hi);
        myrow[j] = make_float2(fmaxf(lo, 0.f), fmaxf(hi, 0.f));
    }

    // segment heads
    bool ishead = (tid == 0) || (sdst[tid - 1] != d);
    __syncthreads();   // messages + sdst visible
    if (ishead) {
        int i = atomicAdd(&snseg, 1);
        sheads[i] = tid;
    }
    __syncthreads();

    int nseg = snseg;
    int warp = tid >> 5, lane = tid & 31;
    for (int sidx = warp; sidx < nseg; sidx += 4) {
        int a = sheads[sidx];
        int d0 = sdst[a];
        // find run end via ballot sweep
        int b = a + 1;
        while (b < 128) {
            int t = b + lane;
            bool diff = (t >= 128) || (sdst[t] != d0);
            unsigned m = __ballot_sync(0xffffffffu, diff);
            if (m) { b += __ffs(m) - 1; break; }
            b += 32;
        }
        float sx = 0.f, sy = 0.f;
        for (int t = a; t < b; t++) {
            float2 v = *reinterpret_cast<const float2*>(sm + t * 66 + 2 * lane);
            sx += v.x; sy += v.y;
        }
        red_add_v2(g_agg + (size_t)d0 * 64 + 2 * lane, sx, sy);
    }
}

// ---------------------------------------------------------------------------
// K6: fused update+LN (nodeA folded via Wc/bc):
//   acc = x@W3[0:64] + (aggsum*inv)@Wc + b3 + bc*(cnt*inv)
//   y = relu(acc) + x ; LayerNorm -> out
// ---------------------------------------------------------------------------
__global__ void __launch_bounds__(128) nodeB_kernel(
        const float* __restrict__ x,
        const float* __restrict__ W3,
        const float* __restrict__ b3,
        const float* __restrict__ gamma,
        const float* __restrict__ beta,
        float* __restrict__ out) {
    __shared__ ulonglong2 sW[128 * 16];  // 32 KB
    __shared__ float sb3[64], sbc[64], sg[64], sbt[64];
    int tid = threadIdx.x;
    const ulonglong2* W3v = reinterpret_cast<const ulonglong2*>(W3);
    const ulonglong2* Wcv = reinterpret_cast<const ulonglong2*>(g_wc);
    for (int idx = tid; idx < 64 * 16; idx += 128) {
        sW[idx] = W3v[idx];
        sW[64 * 16 + idx] = Wcv[idx];
    }
    if (tid < 64) { sb3[tid] = b3[tid]; sbc[tid] = g_bc[tid]; sg[tid] = gamma[tid]; sbt[tid] = beta[tid]; }
    __syncthreads();

    int n = blockIdx.x * 128 + tid;
    if (n >= N_NODES) return;

    float cnt = (float)g_cnt[n];
    float inv = 1.0f / (cnt + 1e-8f);
    float bs  = cnt * inv;

    u64 acc[32];
    #pragma unroll
    for (int j = 0; j < 32; j++)
        acc[j] = pack2f(fmaf(bs, sbc[2*j], sb3[2*j]), fmaf(bs, sbc[2*j+1], sb3[2*j+1]));

    const float4* xr = reinterpret_cast<const float4*>(x + (size_t)n * 64);
    const float4* ar = reinterpret_cast<const float4*>(g_agg + (size_t)n * 64);

    #pragma unroll 1
    for (int c = 0; c < 4; c++) {
        bool isx = (c < 2);
        const float4* p = isx ? (xr + (c & 1) * 8) : (ar + (c & 1) * 8);
        float v[32];
        #pragma unroll
        for (int j = 0; j < 8; j++) {
            float4 f = p[j];
            v[4*j] = f.x; v[4*j+1] = f.y; v[4*j+2] = f.z; v[4*j+3] = f.w;
        }
        if (!isx) {
            #pragma unroll
            for (int j = 0; j < 32; j++) v[j] *= inv;
        }
        #pragma unroll
        for (int i = 0; i < 32; i++) {
            u64 a = pack2(v[i]);
            #pragma unroll
            for (int j = 0; j < 16; j++) {
                ulonglong2 w = sW[(c * 32 + i) * 16 + j];
                ffma2(acc[2*j], a, w.x);
                ffma2(acc[2*j+1], a, w.y);
            }
        }
    }

    float u[64];
    #pragma unroll
    for (int j = 0; j < 16; j++) {
        float4 f = xr[j];
        float a0, a1, a2, a3;
        unpack2(acc[2*j],   a0, a1);
        unpack2(acc[2*j+1], a2, a3);
        u[4*j]   = fmaxf(a0, 0.0f) + f.x;
        u[4*j+1] = fmaxf(a1, 0.0f) + f.y;
        u[4*j+2] = fmaxf(a2, 0.0f) + f.z;
        u[4*j+3] = fmaxf(a3, 0.0f) + f.w;
    }

    float s = 0.0f, ss = 0.0f;
    #pragma unroll
    for (int j = 0; j < 64; j++) { s += u[j]; ss = fmaf(u[j], u[j], ss); }
    float mu  = s * (1.0f / 64.0f);
    float var = ss * (1.0f / 64.0f) - mu * mu;
    float r   = rsqrtf(var + 1e-5f);

    float4* o = reinterpret_cast<float4*>(out + (size_t)n * 64);
    #pragma unroll
    for (int j = 0; j < 16; j++) {
        float4 v;
        v.x = (u[4*j]   - mu) * r * sg[4*j]   + sbt[4*j];
        v.y = (u[4*j+1] - mu) * r * sg[4*j+1] + sbt[4*j+1];
        v.z = (u[4*j+2] - mu) * r * sg[4*j+2] + sbt[4*j+2];
        v.w = (u[4*j+3] - mu) * r * sg[4*j+3] + sbt[4*j+3];
        o[j] = v;
    }
}

// ---------------------------------------------------------------------------
extern "C" void kernel_launch(void* const* d_in, const int* in_sizes, int n_in,
                              void* d_out, int out_size) {
    const float* x     = (const float*)d_in[0];
    const int*   ei    = (const int*)  d_in[1];
    const float* ef    = (const float*)d_in[2];
    const float* W1    = (const float*)d_in[3];
    const float* b1    = (const float*)d_in[4];
    const float* W2    = (const float*)d_in[5];
    const float* b2    = (const float*)d_in[6];
    const float* W3    = (const float*)d_in[7];
    const float* b3    = (const float*)d_in[8];
    const float* gamma = (const float*)d_in[9];
    const float* beta  = (const float*)d_in[10];
    float* out = (float*)d_out;

    (void)in_sizes; (void)n_in; (void)out_size;

    const int nb128 = (N_NODES + 127) / 128;

    prep_kernel<<<64, 64>>>(W2, W3, b2);
    precompute_kernel<<<nb128, 128>>>(x, W1, b1);
    count_kernel<<<N_EDGES / 256, 256>>>(ei);
    scanA_kernel<<<NB_SCAN, 256>>>();
    scanB_kernel<<<1, 256>>>();
    scanC_kernel<<<NB_SCAN, 256>>>();
    place_kernel<<<N_EDGES / 256, 256>>>(ei);
    aggregate_kernel<<<N_EDGES / 128, 128>>>(ef, W1);
    nodeB_kernel<<<nb128, 128>>>(x, W3, b3, gamma, beta, out);
}